// round 1
// baseline (speedup 1.0000x reference)
#include <cuda_runtime.h>

#define HH 512
#define WW 512
#define NPIX (HH*WW)
#define BS 16

// Per-(batch,direction) projection params: Au(3), Av(3), A0(3), c(3)
__device__ float g_params[BS * 2][12];
__device__ int g_maskmode;  // 0 = 4-byte elements (float32/int32), 1 = 1-byte elements (bool/uint8)

__global__ void setup_kernel(const float* __restrict__ R0, const float* __restrict__ t0,
                             const float* __restrict__ R1, const float* __restrict__ t1,
                             const float* __restrict__ K,
                             const unsigned int* __restrict__ mask_probe,
                             float* __restrict__ out, int out_size)
{
    int t = threadIdx.x;
    if (t < out_size && t < 32) out[t] = 0.0f;

    if (t == 0) {
        // Probe mask dtype. float32 1.0 -> 0x3f800000; int32 -> {0,1}; packed bool bytes -> other.
        bool sawFloat = false, sawBig = false;
        for (int i = 0; i < 16; i++) {
            unsigned int w = mask_probe[i];
            if (w == 0x3f800000u) sawFloat = true;
            else if (w > 1u) sawBig = true;
        }
        g_maskmode = sawFloat ? 0 : (sawBig ? 1 : 0);
    }

    if (t >= 32) return;
    int b = t >> 1;
    int dir = t & 1;

    double k[9];
    for (int i = 0; i < 9; i++) k[i] = (double)K[i];
    double det = k[0]*(k[4]*k[8]-k[5]*k[7]) - k[1]*(k[3]*k[8]-k[5]*k[6]) + k[2]*(k[3]*k[7]-k[4]*k[6]);
    double ki[9];
    ki[0]=(k[4]*k[8]-k[5]*k[7])/det; ki[1]=(k[2]*k[7]-k[1]*k[8])/det; ki[2]=(k[1]*k[5]-k[2]*k[4])/det;
    ki[3]=(k[5]*k[6]-k[3]*k[8])/det; ki[4]=(k[0]*k[8]-k[2]*k[6])/det; ki[5]=(k[2]*k[3]-k[0]*k[5])/det;
    ki[6]=(k[3]*k[7]-k[4]*k[6])/det; ki[7]=(k[1]*k[6]-k[0]*k[7])/det; ki[8]=(k[0]*k[4]-k[1]*k[3])/det;

    // direction 0: source pose (R0,t0) -> dest pose (R1,t1); direction 1: swapped.
    const float* Ra = dir ? (R1 + 9*b) : (R0 + 9*b);
    const float* Rb = dir ? (R0 + 9*b) : (R1 + 9*b);
    const float* ta = dir ? (t1 + 3*b) : (t0 + 3*b);
    const float* tb = dir ? (t0 + 3*b) : (t1 + 3*b);

    // M3 = Rb @ Ra^T   (x' = Rb (Ra^T (d*ray - ta)) + tb)
    double M3[9];
    for (int i = 0; i < 3; i++)
        for (int j = 0; j < 3; j++) {
            double s = 0.0;
            for (int d = 0; d < 3; d++) s += (double)Rb[i*3+d] * (double)Ra[j*3+d];
            M3[i*3+j] = s;
        }
    // M = K @ M3
    double M[9];
    for (int i = 0; i < 3; i++)
        for (int j = 0; j < 3; j++) {
            double s = 0.0;
            for (int d = 0; d < 3; d++) s += k[i*3+d] * M3[d*3+j];
            M[i*3+j] = s;
        }
    // c = K@tb - M@ta
    double c[3];
    for (int i = 0; i < 3; i++) {
        double s = 0.0;
        for (int d = 0; d < 3; d++) s += k[i*3+d]*(double)tb[d] - M[i*3+d]*(double)ta[d];
        c[i] = s;
    }
    // G = M @ Ki ; uvw = depth * (G @ [u,v,1]) + c
    double G[9];
    for (int i = 0; i < 3; i++)
        for (int j = 0; j < 3; j++) {
            double s = 0.0;
            for (int d = 0; d < 3; d++) s += M[i*3+d] * ki[d*3+j];
            G[i*3+j] = s;
        }

    float* P = g_params[t];
    P[0] = (float)G[0]; P[1] = (float)G[3]; P[2] = (float)G[6];   // Au = G[:,0]
    P[3] = (float)G[1]; P[4] = (float)G[4]; P[5] = (float)G[7];   // Av = G[:,1]
    P[6] = (float)G[2]; P[7] = (float)G[5]; P[8] = (float)G[8];   // A0 = G[:,2]
    P[9] = (float)c[0]; P[10] = (float)c[1]; P[11] = (float)c[2];
}

__inline__ __device__ float warp_sum(float v) {
    #pragma unroll
    for (int o = 16; o > 0; o >>= 1) v += __shfl_down_sync(0xffffffffu, v, o);
    return v;
}

__global__ __launch_bounds__(256)
void loss_kernel(const float* __restrict__ d0, const float* __restrict__ d1,
                 const float* __restrict__ r0, const float* __restrict__ r1,
                 const void* __restrict__ m0, const void* __restrict__ m1,
                 float* __restrict__ out)
{
    const int b   = blockIdx.y;
    const int dir = blockIdx.z;

    const float* ds = dir ? d1 : d0;   // source depth
    const float* dd = dir ? d0 : d1;   // dest depth (gathered)
    const float* rs = dir ? r1 : r0;   // source rgb
    const float* rd = dir ? r0 : r1;   // dest rgb (gathered)
    const void*  ms = dir ? m1 : m0;   // source mask

    const float* P = g_params[b*2 + dir];
    const float Au0=P[0], Au1=P[1], Au2=P[2];
    const float Av0=P[3], Av1=P[4], Av2=P[5];
    const float A00=P[6], A01=P[7], A02=P[8];
    const float c0 =P[9], c1 =P[10], c2 =P[11];
    const int mode = g_maskmode;

    const int base  = b * NPIX;
    const int base3 = b * 3 * NPIX;

    float sd = 0.0f, sr = 0.0f;
    const int stride = gridDim.x * blockDim.x;

    for (int p = blockIdx.x * blockDim.x + threadIdx.x; p < NPIX; p += stride) {
        bool m;
        if (mode) m = ((const unsigned char*)ms)[base + p] != 0;
        else      m = ((const unsigned int*)ms)[base + p] != 0u;
        if (!m) continue;

        float dep = __ldg(ds + base + p);
        float u = (float)(p & (WW - 1));
        float v = (float)(p >> 9);

        float X = fmaf(dep, fmaf(Au0, u, fmaf(Av0, v, A00)), c0);
        float Y = fmaf(dep, fmaf(Au1, u, fmaf(Av1, v, A01)), c1);
        float Z = fmaf(dep, fmaf(Au2, u, fmaf(Av2, v, A02)), c2);

        float den = fmaxf(Z, 0.0f) + 1e-12f;
        float xs = (X / den) * (512.0f / 511.0f) - 0.5f;
        float ys = (Y / den) * (512.0f / 511.0f) - 0.5f;
        xs = fminf(fmaxf(xs, 0.0f), 511.0f);
        ys = fminf(fmaxf(ys, 0.0f), 511.0f);

        float x0f = floorf(xs), y0f = floorf(ys);
        float fx = xs - x0f, fy = ys - y0f;
        int x0 = (int)x0f, y0 = (int)y0f;
        int x1 = min(x0 + 1, WW - 1);
        int y1 = min(y0 + 1, HH - 1);

        float w00 = (1.0f - fx) * (1.0f - fy);
        float w01 = fx * (1.0f - fy);
        float w10 = (1.0f - fx) * fy;
        float w11 = fx * fy;

        int row0 = base + y0 * WW;
        int row1 = base + y1 * WW;
        float dsm = w00 * __ldg(dd + row0 + x0) + w01 * __ldg(dd + row0 + x1)
                  + w10 * __ldg(dd + row1 + x0) + w11 * __ldg(dd + row1 + x1);

        float ld = fabsf(Z - dsm);
        if (!(ld < 0.1f)) continue;   // clamp mask kills both losses

        sd += ld;

        float lr = 0.0f;
        #pragma unroll
        for (int cch = 0; cch < 3; cch++) {
            int o = base3 + cch * NPIX;
            float sv = __ldg(rs + o + p);
            int ro0 = o + y0 * WW;
            int ro1 = o + y1 * WW;
            float sm = w00 * __ldg(rd + ro0 + x0) + w01 * __ldg(rd + ro0 + x1)
                     + w10 * __ldg(rd + ro1 + x0) + w11 * __ldg(rd + ro1 + x1);
            lr += fabsf(sv - sm);
        }
        sr += lr * (1.0f / 3.0f);
    }

    // Block reduction
    sd = warp_sum(sd);
    sr = warp_sum(sr);
    __shared__ float sD[8], sR[8];
    int lane = threadIdx.x & 31, wid = threadIdx.x >> 5;
    if (lane == 0) { sD[wid] = sd; sR[wid] = sr; }
    __syncthreads();
    if (threadIdx.x == 0) {
        float td = 0.0f, tr = 0.0f;
        #pragma unroll
        for (int i = 0; i < 8; i++) { td += sD[i]; tr += sR[i]; }
        const float invN = 1.0f / (float)NPIX;
        atomicAdd(out + b,      td * invN);
        atomicAdd(out + 16 + b, tr * invN);
    }
}

extern "C" void kernel_launch(void* const* d_in, const int* in_sizes, int n_in,
                              void* d_out, int out_size)
{
    const float* depth0 = (const float*)d_in[0];
    const float* depth1 = (const float*)d_in[1];
    const float* R0     = (const float*)d_in[2];
    const float* t0     = (const float*)d_in[3];
    const float* R1     = (const float*)d_in[4];
    const float* t1     = (const float*)d_in[5];
    const float* rgb0   = (const float*)d_in[6];
    const float* rgb1   = (const float*)d_in[7];
    const void*  mask0  = d_in[8];
    const void*  mask1  = d_in[9];
    const float* K      = (const float*)d_in[10];
    float* out = (float*)d_out;

    setup_kernel<<<1, 64>>>(R0, t0, R1, t1, K, (const unsigned int*)mask0, out, out_size);

    dim3 grid(64, BS, 2);
    loss_kernel<<<grid, 256>>>(depth0, depth1, rgb0, rgb1, mask0, mask1, out);
}

// round 3
// speedup vs baseline: 1.0643x; 1.0643x over previous
#include <cuda_runtime.h>

#define HH 512
#define WW 512
#define NPIX (HH*WW)
#define BS 16

// Per-(batch,direction) projection params: Au(3), Av(3), A0(3), c(3)
__device__ float g_params[BS * 2][12];
__device__ int g_maskmode;  // 0 = 4-byte elements (float32/int32), 1 = 1-byte elements (bool/uint8)

__global__ void setup_kernel(const float* __restrict__ R0, const float* __restrict__ t0,
                             const float* __restrict__ R1, const float* __restrict__ t1,
                             const float* __restrict__ K,
                             const unsigned int* __restrict__ mask_probe,
                             float* __restrict__ out, int out_size)
{
    int t = threadIdx.x;
    if (t < out_size && t < 32) out[t] = 0.0f;

    if (t == 0) {
        bool sawFloat = false, sawBig = false;
        for (int i = 0; i < 16; i++) {
            unsigned int w = mask_probe[i];
            if (w == 0x3f800000u) sawFloat = true;
            else if (w > 1u) sawBig = true;
        }
        g_maskmode = sawFloat ? 0 : (sawBig ? 1 : 0);
    }

    if (t >= 32) return;
    int b = t >> 1;
    int dir = t & 1;

    double k[9];
    for (int i = 0; i < 9; i++) k[i] = (double)K[i];
    double det = k[0]*(k[4]*k[8]-k[5]*k[7]) - k[1]*(k[3]*k[8]-k[5]*k[6]) + k[2]*(k[3]*k[7]-k[4]*k[6]);
    double ki[9];
    ki[0]=(k[4]*k[8]-k[5]*k[7])/det; ki[1]=(k[2]*k[7]-k[1]*k[8])/det; ki[2]=(k[1]*k[5]-k[2]*k[4])/det;
    ki[3]=(k[5]*k[6]-k[3]*k[8])/det; ki[4]=(k[0]*k[8]-k[2]*k[6])/det; ki[5]=(k[2]*k[3]-k[0]*k[5])/det;
    ki[6]=(k[3]*k[7]-k[4]*k[6])/det; ki[7]=(k[1]*k[6]-k[0]*k[7])/det; ki[8]=(k[0]*k[4]-k[1]*k[3])/det;

    const float* Ra = dir ? (R1 + 9*b) : (R0 + 9*b);
    const float* Rb = dir ? (R0 + 9*b) : (R1 + 9*b);
    const float* ta = dir ? (t1 + 3*b) : (t0 + 3*b);
    const float* tb = dir ? (t0 + 3*b) : (t1 + 3*b);

    double M3[9];
    for (int i = 0; i < 3; i++)
        for (int j = 0; j < 3; j++) {
            double s = 0.0;
            for (int d = 0; d < 3; d++) s += (double)Rb[i*3+d] * (double)Ra[j*3+d];
            M3[i*3+j] = s;
        }
    double M[9];
    for (int i = 0; i < 3; i++)
        for (int j = 0; j < 3; j++) {
            double s = 0.0;
            for (int d = 0; d < 3; d++) s += k[i*3+d] * M3[d*3+j];
            M[i*3+j] = s;
        }
    double c[3];
    for (int i = 0; i < 3; i++) {
        double s = 0.0;
        for (int d = 0; d < 3; d++) s += k[i*3+d]*(double)tb[d] - M[i*3+d]*(double)ta[d];
        c[i] = s;
    }
    double G[9];
    for (int i = 0; i < 3; i++)
        for (int j = 0; j < 3; j++) {
            double s = 0.0;
            for (int d = 0; d < 3; d++) s += M[i*3+d] * ki[d*3+j];
            G[i*3+j] = s;
        }

    float* P = g_params[t];
    P[0] = (float)G[0]; P[1] = (float)G[3]; P[2] = (float)G[6];
    P[3] = (float)G[1]; P[4] = (float)G[4]; P[5] = (float)G[7];
    P[6] = (float)G[2]; P[7] = (float)G[5]; P[8] = (float)G[8];
    P[9] = (float)c[0]; P[10] = (float)c[1]; P[11] = (float)c[2];
}

__inline__ __device__ float warp_sum(float v) {
    #pragma unroll
    for (int o = 16; o > 0; o >>= 1) v += __shfl_down_sync(0xffffffffu, v, o);
    return v;
}

__global__ __launch_bounds__(256)
void loss_kernel(const float* __restrict__ d0, const float* __restrict__ d1,
                 const float* __restrict__ r0, const float* __restrict__ r1,
                 const void* __restrict__ m0, const void* __restrict__ m1,
                 float* __restrict__ out)
{
    const int b   = blockIdx.y;
    const int dir = blockIdx.z;

    const float* ds = dir ? d1 : d0;
    const float* dd = dir ? d0 : d1;
    const float* rs = dir ? r1 : r0;
    const float* rd = dir ? r0 : r1;
    const void*  ms = dir ? m1 : m0;

    const float* P = g_params[b*2 + dir];
    const float Au0=P[0], Au1=P[1], Au2=P[2];
    const float Av0=P[3], Av1=P[4], Av2=P[5];
    const float A00=P[6], A01=P[7], A02=P[8];
    const float c0 =P[9], c1 =P[10], c2 =P[11];
    const int mode = g_maskmode;

    const int base  = b * NPIX;
    const int base3 = b * 3 * NPIX;

    const float4* dsv = (const float4*)(ds + base);
    const float4* rsv0 = (const float4*)(rs + base3);
    const float4* rsv1 = (const float4*)(rs + base3 + NPIX);
    const float4* rsv2 = (const float4*)(rs + base3 + 2*NPIX);

    float sd = 0.0f, sr = 0.0f;
    const int nq = NPIX / 4;
    const int stride = gridDim.x * blockDim.x;

    for (int q = blockIdx.x * blockDim.x + threadIdx.x; q < nq; q += stride) {
        const int p0 = q << 2;

        // ---- Phase A: coherent vector loads ----
        float4 dep4 = __ldg(dsv + q);
        float dep[4] = {dep4.x, dep4.y, dep4.z, dep4.w};

        bool m[4];
        if (mode) {
            uchar4 u4 = __ldg((const uchar4*)((const unsigned char*)ms + base) + q);
            m[0] = u4.x != 0; m[1] = u4.y != 0; m[2] = u4.z != 0; m[3] = u4.w != 0;
        } else {
            uint4 u4 = __ldg((const uint4*)((const unsigned int*)ms + base) + q);
            m[0] = u4.x != 0u; m[1] = u4.y != 0u; m[2] = u4.z != 0u; m[3] = u4.w != 0u;
        }

        // 4 consecutive pixels share a row (WW=512, p0 aligned to 4)
        const float v  = (float)(p0 >> 9);
        const float u0 = (float)(p0 & 511);
        const float bX = fmaf(Av0, v, A00);
        const float bY = fmaf(Av1, v, A01);
        const float bZ = fmaf(Av2, v, A02);

        // ---- Phase B: projections for all 4 pixels ----
        float Z[4], w00[4], w01[4], w10[4], w11[4];
        int i00[4], i01[4], i10[4], i11[4];
        #pragma unroll
        for (int i = 0; i < 4; i++) {
            float u = u0 + (float)i;
            float X = fmaf(dep[i], fmaf(Au0, u, bX), c0);
            float Y = fmaf(dep[i], fmaf(Au1, u, bY), c1);
            float Zi = fmaf(dep[i], fmaf(Au2, u, bZ), c2);
            Z[i] = Zi;

            float inv = 1.0f / (fmaxf(Zi, 0.0f) + 1e-12f);
            float xs = fmaf(X * inv, 512.0f / 511.0f, -0.5f);
            float ys = fmaf(Y * inv, 512.0f / 511.0f, -0.5f);
            xs = fminf(fmaxf(xs, 0.0f), 511.0f);
            ys = fminf(fmaxf(ys, 0.0f), 511.0f);

            float x0f = floorf(xs), y0f = floorf(ys);
            float fx = xs - x0f, fy = ys - y0f;
            int x0 = (int)x0f, y0 = (int)y0f;
            int x1 = min(x0 + 1, WW - 1);
            int y1 = min(y0 + 1, HH - 1);

            w00[i] = (1.0f - fx) * (1.0f - fy);
            w01[i] = fx * (1.0f - fy);
            w10[i] = (1.0f - fx) * fy;
            w11[i] = fx * fy;

            int row0 = base + y0 * WW;
            int row1 = base + y1 * WW;
            i00[i] = row0 + x0;  i01[i] = row0 + x1;
            i10[i] = row1 + x0;  i11[i] = row1 + x1;
        }

        // ---- Phase C: issue all 16 depth gathers (predicated by mask) ----
        float g00[4], g01[4], g10[4], g11[4];
        #pragma unroll
        for (int i = 0; i < 4; i++) {
            if (m[i]) {
                g00[i] = __ldg(dd + i00[i]);
                g01[i] = __ldg(dd + i01[i]);
                g10[i] = __ldg(dd + i10[i]);
                g11[i] = __ldg(dd + i11[i]);
            } else {
                g00[i] = g01[i] = g10[i] = g11[i] = 1e30f;
            }
        }

        // ---- Phase D: clamp test + predicated RGB gathers ----
        float ld[4];
        bool pass[4];
        #pragma unroll
        for (int i = 0; i < 4; i++) {
            float dsm = w00[i]*g00[i] + w01[i]*g01[i] + w10[i]*g10[i] + w11[i]*g11[i];
            ld[i] = fabsf(Z[i] - dsm);
            pass[i] = m[i] && (ld[i] < 0.1f);
        }

        bool any = pass[0] | pass[1] | pass[2] | pass[3];
        if (__any_sync(__activemask(), any)) {
            float4 s0 = __ldg(rsv0 + q);
            float4 s1 = __ldg(rsv1 + q);
            float4 s2 = __ldg(rsv2 + q);
            float src[3][4] = {{s0.x,s0.y,s0.z,s0.w},{s1.x,s1.y,s1.z,s1.w},{s2.x,s2.y,s2.z,s2.w}};

            #pragma unroll
            for (int i = 0; i < 4; i++) {
                if (!pass[i]) continue;
                sd += ld[i];
                float lr = 0.0f;
                #pragma unroll
                for (int cch = 0; cch < 3; cch++) {
                    int o = base3 + cch * NPIX - base;  // channel offset relative to depth-base indices
                    float sm = w00[i]*__ldg(rd + o + i00[i]) + w01[i]*__ldg(rd + o + i01[i])
                             + w10[i]*__ldg(rd + o + i10[i]) + w11[i]*__ldg(rd + o + i11[i]);
                    lr += fabsf(src[cch][i] - sm);
                }
                sr += lr * (1.0f / 3.0f);
            }
        }
    }

    sd = warp_sum(sd);
    sr = warp_sum(sr);
    __shared__ float sD[8], sR[8];
    int lane = threadIdx.x & 31, wid = threadIdx.x >> 5;
    if (lane == 0) { sD[wid] = sd; sR[wid] = sr; }
    __syncthreads();
    if (threadIdx.x == 0) {
        float td = 0.0f, tr = 0.0f;
        #pragma unroll
        for (int i = 0; i < 8; i++) { td += sD[i]; tr += sR[i]; }
        const float invN = 1.0f / (float)NPIX;
        atomicAdd(out + b,      td * invN);
        atomicAdd(out + 16 + b, tr * invN);
    }
}

extern "C" void kernel_launch(void* const* d_in, const int* in_sizes, int n_in,
                              void* d_out, int out_size)
{
    const float* depth0 = (const float*)d_in[0];
    const float* depth1 = (const float*)d_in[1];
    const float* R0     = (const float*)d_in[2];
    const float* t0     = (const float*)d_in[3];
    const float* R1     = (const float*)d_in[4];
    const float* t1     = (const float*)d_in[5];
    const float* rgb0   = (const float*)d_in[6];
    const float* rgb1   = (const float*)d_in[7];
    const void*  mask0  = d_in[8];
    const void*  mask1  = d_in[9];
    const float* K      = (const float*)d_in[10];
    float* out = (float*)d_out;

    setup_kernel<<<1, 64>>>(R0, t0, R1, t1, K, (const unsigned int*)mask0, out, out_size);

    dim3 grid(64, BS, 2);
    loss_kernel<<<grid, 256>>>(depth0, depth1, rgb0, rgb1, mask0, mask1, out);
}

// round 4
// speedup vs baseline: 1.5315x; 1.4391x over previous
#include <cuda_runtime.h>

#define HH 512
#define WW 512
#define NPIX (HH*WW)
#define BS 16

// Per-(batch,direction) projection params: Au(3), Av(3), A0(3), c(3)
__device__ float g_params[BS * 2][12];
__device__ int g_maskmode;  // 0 = 4-byte elements (float32/int32), 1 = 1-byte elements (bool/uint8)

__global__ void setup_kernel(const float* __restrict__ R0, const float* __restrict__ t0,
                             const float* __restrict__ R1, const float* __restrict__ t1,
                             const float* __restrict__ K,
                             const unsigned int* __restrict__ mask_probe,
                             float* __restrict__ out, int out_size)
{
    int t = threadIdx.x;
    if (t < out_size && t < 32) out[t] = 0.0f;

    if (t == 0) {
        bool sawFloat = false, sawBig = false;
        for (int i = 0; i < 16; i++) {
            unsigned int w = mask_probe[i];
            if (w == 0x3f800000u) sawFloat = true;
            else if (w > 1u) sawBig = true;
        }
        g_maskmode = sawFloat ? 0 : (sawBig ? 1 : 0);
    }

    if (t >= 32) return;
    int b = t >> 1;
    int dir = t & 1;

    double k[9];
    for (int i = 0; i < 9; i++) k[i] = (double)K[i];
    double det = k[0]*(k[4]*k[8]-k[5]*k[7]) - k[1]*(k[3]*k[8]-k[5]*k[6]) + k[2]*(k[3]*k[7]-k[4]*k[6]);
    double ki[9];
    ki[0]=(k[4]*k[8]-k[5]*k[7])/det; ki[1]=(k[2]*k[7]-k[1]*k[8])/det; ki[2]=(k[1]*k[5]-k[2]*k[4])/det;
    ki[3]=(k[5]*k[6]-k[3]*k[8])/det; ki[4]=(k[0]*k[8]-k[2]*k[6])/det; ki[5]=(k[2]*k[3]-k[0]*k[5])/det;
    ki[6]=(k[3]*k[7]-k[4]*k[6])/det; ki[7]=(k[1]*k[6]-k[0]*k[7])/det; ki[8]=(k[0]*k[4]-k[1]*k[3])/det;

    const float* Ra = dir ? (R1 + 9*b) : (R0 + 9*b);
    const float* Rb = dir ? (R0 + 9*b) : (R1 + 9*b);
    const float* ta = dir ? (t1 + 3*b) : (t0 + 3*b);
    const float* tb = dir ? (t0 + 3*b) : (t1 + 3*b);

    double M3[9];
    for (int i = 0; i < 3; i++)
        for (int j = 0; j < 3; j++) {
            double s = 0.0;
            for (int d = 0; d < 3; d++) s += (double)Rb[i*3+d] * (double)Ra[j*3+d];
            M3[i*3+j] = s;
        }
    double M[9];
    for (int i = 0; i < 3; i++)
        for (int j = 0; j < 3; j++) {
            double s = 0.0;
            for (int d = 0; d < 3; d++) s += k[i*3+d] * M3[d*3+j];
            M[i*3+j] = s;
        }
    double c[3];
    for (int i = 0; i < 3; i++) {
        double s = 0.0;
        for (int d = 0; d < 3; d++) s += k[i*3+d]*(double)tb[d] - M[i*3+d]*(double)ta[d];
        c[i] = s;
    }
    double G[9];
    for (int i = 0; i < 3; i++)
        for (int j = 0; j < 3; j++) {
            double s = 0.0;
            for (int d = 0; d < 3; d++) s += M[i*3+d] * ki[d*3+j];
            G[i*3+j] = s;
        }

    float* P = g_params[t];
    P[0] = (float)G[0]; P[1] = (float)G[3]; P[2] = (float)G[6];
    P[3] = (float)G[1]; P[4] = (float)G[4]; P[5] = (float)G[7];
    P[6] = (float)G[2]; P[7] = (float)G[5]; P[8] = (float)G[8];
    P[9] = (float)c[0]; P[10] = (float)c[1]; P[11] = (float)c[2];
}

__inline__ __device__ float warp_sum(float v) {
    #pragma unroll
    for (int o = 16; o > 0; o >>= 1) v += __shfl_down_sync(0xffffffffu, v, o);
    return v;
}

__global__ __launch_bounds__(256, 4)
void loss_kernel(const float* __restrict__ d0, const float* __restrict__ d1,
                 const float* __restrict__ r0, const float* __restrict__ r1,
                 const void* __restrict__ m0, const void* __restrict__ m1,
                 float* __restrict__ out)
{
    const int b   = blockIdx.y;
    const int dir = blockIdx.z;

    const float* ds = dir ? d1 : d0;
    const float* dd = dir ? d0 : d1;
    const float* rs = dir ? r1 : r0;
    const float* rd = dir ? r0 : r1;
    const void*  ms = dir ? m1 : m0;

    const float* P = g_params[b*2 + dir];
    const float Au0=P[0], Au1=P[1], Au2=P[2];
    const float Av0=P[3], Av1=P[4], Av2=P[5];
    const float A00=P[6], A01=P[7], A02=P[8];
    const float c0 =P[9], c1 =P[10], c2 =P[11];
    const int mode = g_maskmode;

    const int base  = b * NPIX;
    const int base3 = b * 3 * NPIX;

    const float4* dsv  = (const float4*)(ds + base);
    const float4* rsv0 = (const float4*)(rs + base3);
    const float4* rsv1 = (const float4*)(rs + base3 + NPIX);
    const float4* rsv2 = (const float4*)(rs + base3 + 2*NPIX);

    float sd = 0.0f, sr = 0.0f;
    const int nq = NPIX / 4;
    const int stride = gridDim.x * blockDim.x;

    for (int q = blockIdx.x * blockDim.x + threadIdx.x; q < nq; q += stride) {
        const int p0 = q << 2;

        // ---- coherent vector loads ----
        float4 dep4 = __ldg(dsv + q);
        float dep[4] = {dep4.x, dep4.y, dep4.z, dep4.w};

        bool m[4];
        if (mode) {
            uchar4 u4 = __ldg((const uchar4*)((const unsigned char*)ms + base) + q);
            m[0] = u4.x != 0; m[1] = u4.y != 0; m[2] = u4.z != 0; m[3] = u4.w != 0;
        } else {
            uint4 u4 = __ldg((const uint4*)((const unsigned int*)ms + base) + q);
            m[0] = u4.x != 0u; m[1] = u4.y != 0u; m[2] = u4.z != 0u; m[3] = u4.w != 0u;
        }

        const float v  = (float)(p0 >> 9);
        const float u0 = (float)(p0 & 511);
        const float bX = fmaf(Av0, v, A00);
        const float bY = fmaf(Av1, v, A01);
        const float bZ = fmaf(Av2, v, A02);

        // ---- projections: keep only Z, fx, fy, i00, dx, dyW live ----
        float Z[4], fx[4], fy[4];
        int i00[4], dx[4], dyW[4];
        #pragma unroll
        for (int i = 0; i < 4; i++) {
            float u = u0 + (float)i;
            float X  = fmaf(dep[i], fmaf(Au0, u, bX), c0);
            float Y  = fmaf(dep[i], fmaf(Au1, u, bY), c1);
            float Zi = fmaf(dep[i], fmaf(Au2, u, bZ), c2);
            Z[i] = Zi;

            float inv = 1.0f / (fmaxf(Zi, 0.0f) + 1e-12f);
            float xs = fmaf(X * inv, 512.0f / 511.0f, -0.5f);
            float ys = fmaf(Y * inv, 512.0f / 511.0f, -0.5f);
            xs = fminf(fmaxf(xs, 0.0f), 511.0f);
            ys = fminf(fmaxf(ys, 0.0f), 511.0f);

            float x0f = floorf(xs), y0f = floorf(ys);
            fx[i] = xs - x0f;
            fy[i] = ys - y0f;
            int x0 = (int)x0f, y0 = (int)y0f;
            dx[i]  = (x0 < WW - 1) ? 1 : 0;
            dyW[i] = (y0 < HH - 1) ? WW : 0;
            i00[i] = base + y0 * WW + x0;
        }

        // ---- all 16 depth gathers back-to-back (mask folded into sentinel) ----
        float g00[4], g01[4], g10[4], g11[4];
        #pragma unroll
        for (int i = 0; i < 4; i++) {
            if (m[i]) {
                int a00 = i00[i];
                int a10 = a00 + dyW[i];
                g00[i] = __ldg(dd + a00);
                g01[i] = __ldg(dd + a00 + dx[i]);
                g10[i] = __ldg(dd + a10);
                g11[i] = __ldg(dd + a10 + dx[i]);
            } else {
                g00[i] = g01[i] = g10[i] = g11[i] = 1e30f;
            }
        }

        // ---- clamp test (weights recomputed from fx/fy) ----
        float ld[4];
        bool pass[4];
        #pragma unroll
        for (int i = 0; i < 4; i++) {
            float ofx = 1.0f - fx[i], ofy = 1.0f - fy[i];
            float dsm = ofx*ofy*g00[i] + fx[i]*ofy*g01[i] + ofx*fy[i]*g10[i] + fx[i]*fy[i]*g11[i];
            ld[i] = fabsf(Z[i] - dsm);
            pass[i] = ld[i] < 0.1f;   // sentinel 1e30 auto-fails
        }

        bool any = pass[0] | pass[1] | pass[2] | pass[3];
        if (__any_sync(__activemask(), any)) {
            float4 s0 = __ldg(rsv0 + q);
            float4 s1 = __ldg(rsv1 + q);
            float4 s2 = __ldg(rsv2 + q);
            float src[3][4] = {{s0.x,s0.y,s0.z,s0.w},{s1.x,s1.y,s1.z,s1.w},{s2.x,s2.y,s2.z,s2.w}};

            #pragma unroll
            for (int i = 0; i < 4; i++) {
                if (!pass[i]) continue;
                sd += ld[i];
                float ofx = 1.0f - fx[i], ofy = 1.0f - fy[i];
                float w00 = ofx*ofy, w01 = fx[i]*ofy, w10 = ofx*fy[i], w11 = fx[i]*fy[i];
                int a00 = i00[i] - base;           // pixel offset within image
                int a10 = a00 + dyW[i];
                float lr = 0.0f;
                #pragma unroll
                for (int cch = 0; cch < 3; cch++) {
                    const float* ch = rd + base3 + cch * NPIX;
                    float sm = w00*__ldg(ch + a00)          + w01*__ldg(ch + a00 + dx[i])
                             + w10*__ldg(ch + a10)          + w11*__ldg(ch + a10 + dx[i]);
                    lr += fabsf(src[cch][i] - sm);
                }
                sr += lr * (1.0f / 3.0f);
            }
        }
    }

    sd = warp_sum(sd);
    sr = warp_sum(sr);
    __shared__ float sD[8], sR[8];
    int lane = threadIdx.x & 31, wid = threadIdx.x >> 5;
    if (lane == 0) { sD[wid] = sd; sR[wid] = sr; }
    __syncthreads();
    if (threadIdx.x == 0) {
        float td = 0.0f, tr = 0.0f;
        #pragma unroll
        for (int i = 0; i < 8; i++) { td += sD[i]; tr += sR[i]; }
        const float invN = 1.0f / (float)NPIX;
        atomicAdd(out + b,      td * invN);
        atomicAdd(out + 16 + b, tr * invN);
    }
}

extern "C" void kernel_launch(void* const* d_in, const int* in_sizes, int n_in,
                              void* d_out, int out_size)
{
    const float* depth0 = (const float*)d_in[0];
    const float* depth1 = (const float*)d_in[1];
    const float* R0     = (const float*)d_in[2];
    const float* t0     = (const float*)d_in[3];
    const float* R1     = (const float*)d_in[4];
    const float* t1     = (const float*)d_in[5];
    const float* rgb0   = (const float*)d_in[6];
    const float* rgb1   = (const float*)d_in[7];
    const void*  mask0  = d_in[8];
    const void*  mask1  = d_in[9];
    const float* K      = (const float*)d_in[10];
    float* out = (float*)d_out;

    setup_kernel<<<1, 64>>>(R0, t0, R1, t1, K, (const unsigned int*)mask0, out, out_size);

    dim3 grid(64, BS, 2);
    loss_kernel<<<grid, 256>>>(depth0, depth1, rgb0, rgb1, mask0, mask1, out);
}

// round 5
// speedup vs baseline: 1.7209x; 1.1237x over previous
#include <cuda_runtime.h>

#define HH 512
#define WW 512
#define NPIX (HH*WW)
#define BS 16

// Per-(batch,direction) projection params: Au(3), Av(3), A0(3), c(3)
__device__ float g_params[BS * 2][12];
__device__ int g_maskmode;  // 0 = 4-byte elements (float32/int32), 1 = 1-byte elements (bool/uint8)

__global__ void setup_kernel(const float* __restrict__ R0, const float* __restrict__ t0,
                             const float* __restrict__ R1, const float* __restrict__ t1,
                             const float* __restrict__ K,
                             const unsigned int* __restrict__ mask_probe,
                             float* __restrict__ out, int out_size)
{
    int t = threadIdx.x;
    if (t < out_size && t < 32) out[t] = 0.0f;

    if (t == 0) {
        bool sawFloat = false, sawBig = false;
        for (int i = 0; i < 16; i++) {
            unsigned int w = mask_probe[i];
            if (w == 0x3f800000u) sawFloat = true;
            else if (w > 1u) sawBig = true;
        }
        g_maskmode = sawFloat ? 0 : (sawBig ? 1 : 0);
    }

    if (t >= 32) return;
    int b = t >> 1;
    int dir = t & 1;

    float k[9];
    #pragma unroll
    for (int i = 0; i < 9; i++) k[i] = K[i];
    float det = k[0]*(k[4]*k[8]-k[5]*k[7]) - k[1]*(k[3]*k[8]-k[5]*k[6]) + k[2]*(k[3]*k[7]-k[4]*k[6]);
    float rdet = 1.0f / det;
    float ki[9];
    ki[0]=(k[4]*k[8]-k[5]*k[7])*rdet; ki[1]=(k[2]*k[7]-k[1]*k[8])*rdet; ki[2]=(k[1]*k[5]-k[2]*k[4])*rdet;
    ki[3]=(k[5]*k[6]-k[3]*k[8])*rdet; ki[4]=(k[0]*k[8]-k[2]*k[6])*rdet; ki[5]=(k[2]*k[3]-k[0]*k[5])*rdet;
    ki[6]=(k[3]*k[7]-k[4]*k[6])*rdet; ki[7]=(k[1]*k[6]-k[0]*k[7])*rdet; ki[8]=(k[0]*k[4]-k[1]*k[3])*rdet;

    const float* Ra = dir ? (R1 + 9*b) : (R0 + 9*b);
    const float* Rb = dir ? (R0 + 9*b) : (R1 + 9*b);
    const float* ta = dir ? (t1 + 3*b) : (t0 + 3*b);
    const float* tb = dir ? (t0 + 3*b) : (t1 + 3*b);

    // M3 = Rb @ Ra^T
    float M3[9];
    #pragma unroll
    for (int i = 0; i < 3; i++)
        #pragma unroll
        for (int j = 0; j < 3; j++) {
            float s = 0.0f;
            #pragma unroll
            for (int d = 0; d < 3; d++) s += Rb[i*3+d] * Ra[j*3+d];
            M3[i*3+j] = s;
        }
    // M = K @ M3
    float M[9];
    #pragma unroll
    for (int i = 0; i < 3; i++)
        #pragma unroll
        for (int j = 0; j < 3; j++) {
            float s = 0.0f;
            #pragma unroll
            for (int d = 0; d < 3; d++) s += k[i*3+d] * M3[d*3+j];
            M[i*3+j] = s;
        }
    // c = K@tb - M@ta
    float c[3];
    #pragma unroll
    for (int i = 0; i < 3; i++) {
        float s = 0.0f;
        #pragma unroll
        for (int d = 0; d < 3; d++) s += k[i*3+d]*tb[d] - M[i*3+d]*ta[d];
        c[i] = s;
    }
    // G = M @ Ki
    float G[9];
    #pragma unroll
    for (int i = 0; i < 3; i++)
        #pragma unroll
        for (int j = 0; j < 3; j++) {
            float s = 0.0f;
            #pragma unroll
            for (int d = 0; d < 3; d++) s += M[i*3+d] * ki[d*3+j];
            G[i*3+j] = s;
        }

    float* P = g_params[t];
    P[0] = G[0]; P[1] = G[3]; P[2] = G[6];
    P[3] = G[1]; P[4] = G[4]; P[5] = G[7];
    P[6] = G[2]; P[7] = G[5]; P[8] = G[8];
    P[9] = c[0]; P[10] = c[1]; P[11] = c[2];
}

__inline__ __device__ float warp_sum(float v) {
    #pragma unroll
    for (int o = 16; o > 0; o >>= 1) v += __shfl_down_sync(0xffffffffu, v, o);
    return v;
}

__global__ __launch_bounds__(256, 4)
void loss_kernel(const float* __restrict__ d0, const float* __restrict__ d1,
                 const float* __restrict__ r0, const float* __restrict__ r1,
                 const void* __restrict__ m0, const void* __restrict__ m1,
                 float* __restrict__ out)
{
    const int b   = blockIdx.y;
    const int dir = blockIdx.z;

    const float* ds = dir ? d1 : d0;
    const float* dd = dir ? d0 : d1;
    const float* rs = dir ? r1 : r0;
    const float* rd = dir ? r0 : r1;
    const void*  ms = dir ? m1 : m0;

    const float* P = g_params[b*2 + dir];
    const float Au0=P[0], Au1=P[1], Au2=P[2];
    const float Av0=P[3], Av1=P[4], Av2=P[5];
    const float A00=P[6], A01=P[7], A02=P[8];
    const float c0 =P[9], c1 =P[10], c2 =P[11];
    const int mode = g_maskmode;

    const int base  = b * NPIX;
    const int base3 = b * 3 * NPIX;

    const float4* dsv = (const float4*)(ds + base);

    float sd = 0.0f, sr = 0.0f;
    const int nq = NPIX / 4;
    const int stride = gridDim.x * blockDim.x;

    for (int q = blockIdx.x * blockDim.x + threadIdx.x; q < nq; q += stride) {
        const int p0 = q << 2;

        // ---- coherent streaming loads (evict-first: no reuse) ----
        float4 dep4 = __ldcs(dsv + q);
        float dep[4] = {dep4.x, dep4.y, dep4.z, dep4.w};

        bool m[4];
        if (mode) {
            uchar4 u4 = __ldcs((const uchar4*)((const unsigned char*)ms + base) + q);
            m[0] = u4.x != 0; m[1] = u4.y != 0; m[2] = u4.z != 0; m[3] = u4.w != 0;
        } else {
            uint4 u4 = __ldcs((const uint4*)((const unsigned int*)ms + base) + q);
            m[0] = u4.x != 0u; m[1] = u4.y != 0u; m[2] = u4.z != 0u; m[3] = u4.w != 0u;
        }

        const float v  = (float)(p0 >> 9);
        const float u0 = (float)(p0 & 511);
        const float bX = fmaf(Av0, v, A00);
        const float bY = fmaf(Av1, v, A01);
        const float bZ = fmaf(Av2, v, A02);

        // ---- projections: keep only Z, fx, fy, i00, dx, dyW live ----
        float Z[4], fx[4], fy[4];
        int i00[4], dx[4], dyW[4];
        #pragma unroll
        for (int i = 0; i < 4; i++) {
            float u = u0 + (float)i;
            float X  = fmaf(dep[i], fmaf(Au0, u, bX), c0);
            float Y  = fmaf(dep[i], fmaf(Au1, u, bY), c1);
            float Zi = fmaf(dep[i], fmaf(Au2, u, bZ), c2);
            Z[i] = Zi;

            float inv = 1.0f / (fmaxf(Zi, 0.0f) + 1e-12f);
            float xs = fmaf(X * inv, 512.0f / 511.0f, -0.5f);
            float ys = fmaf(Y * inv, 512.0f / 511.0f, -0.5f);
            xs = fminf(fmaxf(xs, 0.0f), 511.0f);
            ys = fminf(fmaxf(ys, 0.0f), 511.0f);

            float x0f = floorf(xs), y0f = floorf(ys);
            fx[i] = xs - x0f;
            fy[i] = ys - y0f;
            int x0 = (int)x0f, y0 = (int)y0f;
            dx[i]  = (x0 < WW - 1) ? 1 : 0;
            dyW[i] = (y0 < HH - 1) ? WW : 0;
            i00[i] = base + y0 * WW + x0;
        }

        // ---- all 16 depth gathers back-to-back (mask folded into sentinel) ----
        float g00[4], g01[4], g10[4], g11[4];
        #pragma unroll
        for (int i = 0; i < 4; i++) {
            if (m[i]) {
                int a00 = i00[i];
                int a10 = a00 + dyW[i];
                g00[i] = __ldg(dd + a00);
                g01[i] = __ldg(dd + a00 + dx[i]);
                g10[i] = __ldg(dd + a10);
                g11[i] = __ldg(dd + a10 + dx[i]);
            } else {
                g00[i] = g01[i] = g10[i] = g11[i] = 1e30f;
            }
        }

        // ---- clamp test + predicated per-pixel RGB work ----
        #pragma unroll
        for (int i = 0; i < 4; i++) {
            float ofx = 1.0f - fx[i], ofy = 1.0f - fy[i];
            float w00 = ofx*ofy, w01 = fx[i]*ofy, w10 = ofx*fy[i], w11 = fx[i]*fy[i];
            float dsm = w00*g00[i] + w01*g01[i] + w10*g10[i] + w11*g11[i];
            float ld = fabsf(Z[i] - dsm);
            if (ld < 0.1f) {               // sentinel 1e30 auto-fails
                sd += ld;
                int a00 = i00[i] - base;   // pixel offset within image
                int a10 = a00 + dyW[i];
                int p = p0 + i;
                float lr = 0.0f;
                #pragma unroll
                for (int cch = 0; cch < 3; cch++) {
                    const int o = base3 + cch * NPIX;
                    float sv = __ldcs(rs + o + p);
                    const float* ch = rd + o;
                    float sm = w00*__ldg(ch + a00)       + w01*__ldg(ch + a00 + dx[i])
                             + w10*__ldg(ch + a10)       + w11*__ldg(ch + a10 + dx[i]);
                    lr += fabsf(sv - sm);
                }
                sr += lr * (1.0f / 3.0f);
            }
        }
    }

    sd = warp_sum(sd);
    sr = warp_sum(sr);
    __shared__ float sD[8], sR[8];
    int lane = threadIdx.x & 31, wid = threadIdx.x >> 5;
    if (lane == 0) { sD[wid] = sd; sR[wid] = sr; }
    __syncthreads();
    if (threadIdx.x == 0) {
        float td = 0.0f, tr = 0.0f;
        #pragma unroll
        for (int i = 0; i < 8; i++) { td += sD[i]; tr += sR[i]; }
        const float invN = 1.0f / (float)NPIX;
        atomicAdd(out + b,      td * invN);
        atomicAdd(out + 16 + b, tr * invN);
    }
}

extern "C" void kernel_launch(void* const* d_in, const int* in_sizes, int n_in,
                              void* d_out, int out_size)
{
    const float* depth0 = (const float*)d_in[0];
    const float* depth1 = (const float*)d_in[1];
    const float* R0     = (const float*)d_in[2];
    const float* t0     = (const float*)d_in[3];
    const float* R1     = (const float*)d_in[4];
    const float* t1     = (const float*)d_in[5];
    const float* rgb0   = (const float*)d_in[6];
    const float* rgb1   = (const float*)d_in[7];
    const void*  mask0  = d_in[8];
    const void*  mask1  = d_in[9];
    const float* K      = (const float*)d_in[10];
    float* out = (float*)d_out;

    setup_kernel<<<1, 64>>>(R0, t0, R1, t1, K, (const unsigned int*)mask0, out, out_size);

    dim3 grid(64, BS, 2);
    loss_kernel<<<grid, 256>>>(depth0, depth1, rgb0, rgb1, mask0, mask1, out);
}